// round 14
// baseline (speedup 1.0000x reference)
#include <cuda_runtime.h>
#include <cstdint>

// Fused Tucker linear layer, fp32, register-blocked vectorized LDS.
// Grid: 256 CTAs x 256 threads, 16 samples/CTA, 2 CTAs/SM.

#define THREADS 256
#define SPB 16
#define SB  4

// smem float offsets
//  zs  : [512][20]                              -> 10240
//  usb : 8192 : ph1 t1 [4][2048] ; ph2/3 U[16][512]
//  scr : 8256 : ph1 x-stage 8192 / t2 4096 ; ph2 tile [16][516] ; ph3 s1 4096
//  fs  : 768  : f0|f1|f2|f3|f4|f5 (128 each)
#define ZS_OFF   0
#define US_OFF   10240
#define SCR_OFF  (10240 + 8192)
#define FS_OFF   (SCR_OFF + 8256)
#define SMEM_FLOATS (FS_OFF + 768)
#define SMEM_BYTES  (SMEM_FLOATS * 4)

__global__ __launch_bounds__(THREADS, 2) void tucker_fused(
    const float* __restrict__ x, const float* __restrict__ core,
    const float* __restrict__ f0, const float* __restrict__ f1,
    const float* __restrict__ f2, const float* __restrict__ f3,
    const float* __restrict__ f4, const float* __restrict__ f5,
    const float* __restrict__ bias, float* __restrict__ y)
{
    extern __shared__ float sm[];
    float* zs  = sm + ZS_OFF;
    float* usb = sm + US_OFF;
    float* scr = sm + SCR_OFF;
    float* fs  = sm + FS_OFF;

    const int tid = threadIdx.x;
    const int s0 = blockIdx.x * SPB;

    if (tid < 128) {
        fs[tid]       = f0[tid];
        fs[128 + tid] = f1[tid];
        fs[256 + tid] = f2[tid];
        fs[384 + tid] = f3[tid];
        fs[512 + tid] = f4[tid];
        fs[640 + tid] = f5[tid];
    }
    __syncthreads();

    // ================= PHASE 1: in-side -> zs[k][s] =================
    {
        float* t1 = usb;   // [4][256][8] : (sl<<11) + de*8 + nn

        for (int sb = 0; sb < SPB; sb += SB) {
#pragma unroll
            for (int pair = 0; pair < 2; pair++) {
                // stage 2 samples (coalesced)
                float4* xs4 = (float4*)scr;
#pragma unroll
                for (int i = 0; i < 8; i++) {
                    int g = i * THREADS + tid;
                    int sl = g >> 10;
                    const float4* xp = (const float4*)(x + ((size_t)(s0 + sb + pair * 2 + sl) << 12));
                    xs4[g] = xp[g & 1023];
                }
                __syncthreads();
                // 1a: thread = (sl2, 2 consecutive de); computes 2x8 outputs
                {
                    int sl2 = tid >> 7, de0 = (tid & 127) * 2;
                    const float* xb = scr + sl2 * 4096 + de0 * 16;
                    float xv[32];
#pragma unroll
                    for (int q = 0; q < 8; q++)
                        *(float4*)&xv[q * 4] = *(const float4*)&xb[q * 4];
                    float acc[2][8];
#pragma unroll
                    for (int h = 0; h < 2; h++)
#pragma unroll
                        for (int nn = 0; nn < 8; nn++) acc[h][nn] = 0.f;
#pragma unroll
                    for (int f = 0; f < 16; f++) {
                        float4 fa = *(const float4*)&fs[640 + f * 8];
                        float4 fb = *(const float4*)&fs[640 + f * 8 + 4];
#pragma unroll
                        for (int h = 0; h < 2; h++) {
                            float xf = xv[h * 16 + f];
                            acc[h][0] += xf * fa.x; acc[h][1] += xf * fa.y;
                            acc[h][2] += xf * fa.z; acc[h][3] += xf * fa.w;
                            acc[h][4] += xf * fb.x; acc[h][5] += xf * fb.y;
                            acc[h][6] += xf * fb.z; acc[h][7] += xf * fb.w;
                        }
                    }
                    float* ob = t1 + ((pair * 2 + sl2) << 11) + de0 * 8;
#pragma unroll
                    for (int h = 0; h < 2; h++) {
                        *(float4*)&ob[h * 8]     = make_float4(acc[h][0], acc[h][1], acc[h][2], acc[h][3]);
                        *(float4*)&ob[h * 8 + 4] = make_float4(acc[h][4], acc[h][5], acc[h][6], acc[h][7]);
                    }
                }
                __syncthreads();
            }
            // 1b: t2[sl][d][m][nn] = sum_e f4[e][m] * t1[sl][d*16+e][nn]
            //     thread = (sl, d, nnq, mh): 4 m x 4 nn outputs
            float* t2 = scr;   // [4][16][8][8]
            {
                int mh = tid & 1, nnq = (tid >> 1) & 1, d = (tid >> 2) & 15, sl = tid >> 6;
                const float* tb = t1 + (sl << 11) + d * 128 + nnq * 4;
                float acc[4][4];
#pragma unroll
                for (int mi = 0; mi < 4; mi++)
#pragma unroll
                    for (int q = 0; q < 4; q++) acc[mi][q] = 0.f;
#pragma unroll
                for (int e = 0; e < 16; e++) {
                    float4 tv = *(const float4*)&tb[e * 8];
                    float4 fv = *(const float4*)&fs[512 + e * 8 + mh * 4];
                    acc[0][0] += fv.x * tv.x; acc[0][1] += fv.x * tv.y;
                    acc[0][2] += fv.x * tv.z; acc[0][3] += fv.x * tv.w;
                    acc[1][0] += fv.y * tv.x; acc[1][1] += fv.y * tv.y;
                    acc[1][2] += fv.y * tv.z; acc[1][3] += fv.y * tv.w;
                    acc[2][0] += fv.z * tv.x; acc[2][1] += fv.z * tv.y;
                    acc[2][2] += fv.z * tv.z; acc[2][3] += fv.z * tv.w;
                    acc[3][0] += fv.w * tv.x; acc[3][1] += fv.w * tv.y;
                    acc[3][2] += fv.w * tv.z; acc[3][3] += fv.w * tv.w;
                }
                float* tp = t2 + sl * 1024 + d * 64 + mh * 32 + nnq * 4;
#pragma unroll
                for (int mi = 0; mi < 4; mi++)
                    *(float4*)&tp[mi * 8] = make_float4(acc[mi][0], acc[mi][1], acc[mi][2], acc[mi][3]);
            }
            __syncthreads();
            // 1c: zs[k][sb+sl] = sum_d f3[d][l] * t2[sl][d][mn], k = l*64+mn
            //     thread = (sl, mnq, lh): 2 l x 4 mn outputs
            {
                int lh = tid & 3, mnq = (tid >> 2) & 15, sl = tid >> 6;
                const float* tb = t2 + sl * 1024 + mnq * 4;
                float acc[2][4];
#pragma unroll
                for (int li = 0; li < 2; li++)
#pragma unroll
                    for (int q = 0; q < 4; q++) acc[li][q] = 0.f;
#pragma unroll
                for (int d = 0; d < 16; d++) {
                    float4 tv = *(const float4*)&tb[d * 64];
                    float2 fv = *(const float2*)&fs[384 + d * 8 + lh * 2];
                    acc[0][0] += fv.x * tv.x; acc[0][1] += fv.x * tv.y;
                    acc[0][2] += fv.x * tv.z; acc[0][3] += fv.x * tv.w;
                    acc[1][0] += fv.y * tv.x; acc[1][1] += fv.y * tv.y;
                    acc[1][2] += fv.y * tv.z; acc[1][3] += fv.y * tv.w;
                }
#pragma unroll
                for (int li = 0; li < 2; li++)
#pragma unroll
                    for (int q = 0; q < 4; q++) {
                        int k = (lh * 2 + li) * 64 + mnq * 4 + q;
                        zs[k * 20 + sb + sl] = acc[li][q];
                    }
            }
            __syncthreads();
        }
    }

    // ================= PHASE 2: U[16,512] = Z @ core^T (conflict-free tile) =====
    // tile[16][516]: element (kk, o) at kk*516 + (o ^ ((kk>>2)*8))
    {
        float* tile = scr;
        const int sg = tid >> 7;
        const int og = tid & 127;
        const int o0 = tid >> 2;
        const int kq = tid & 3;
        const int sbase = kq * 2064 + (o0 ^ (kq * 8));
        int lb[4];
        lb[0] = og * 4;
        lb[1] = (og * 4) ^ 8;
        lb[2] = (og * 4) ^ 16;
        lb[3] = (og * 4) ^ 24;

        float acc[8][4];
#pragma unroll
        for (int s = 0; s < 8; s++)
#pragma unroll
            for (int o = 0; o < 4; o++) acc[s][o] = 0.f;

        const float4* core4 = (const float4*)core;
        float4 pf[8];
#pragma unroll
        for (int i = 0; i < 8; i++)
            pf[i] = core4[(o0 + i * 64) * 128 + kq];

#pragma unroll 1
        for (int kt = 0; kt < 32; kt++) {
            __syncthreads();
#pragma unroll
            for (int i = 0; i < 8; i++) {
                float* sp = tile + sbase + i * 64;
                sp[0]    = pf[i].x;
                sp[516]  = pf[i].y;
                sp[1032] = pf[i].z;
                sp[1548] = pf[i].w;
            }
            __syncthreads();
            if (kt < 31) {
#pragma unroll
                for (int i = 0; i < 8; i++)
                    pf[i] = core4[(o0 + i * 64) * 128 + (kt + 1) * 4 + kq];
            }
#pragma unroll
            for (int kk = 0; kk < 16; kk++) {
                const float* ar = zs + (kt * 16 + kk) * 20 + sg * 8;
                float a[8];
                *(float4*)&a[0] = *(const float4*)ar;
                *(float4*)&a[4] = *(const float4*)(ar + 4);
                float b[4];
                *(float4*)b = *(const float4*)&tile[kk * 516 + lb[kk >> 2]];
#pragma unroll
                for (int s = 0; s < 8; s++)
#pragma unroll
                    for (int o = 0; o < 4; o++) acc[s][o] += a[s] * b[o];
            }
        }
        __syncthreads();
#pragma unroll
        for (int s = 0; s < 8; s++)
            *(float4*)&usb[(sg * 8 + s) * 512 + og * 4] = *(float4*)acc[s];
        __syncthreads();
    }

    // ================= PHASE 3: out-side + bias -> y =================
    {
        float* s1 = scr;   // [4][16][8][8] : sl*1024 + a*64 + j*8 + k

        for (int sb = 0; sb < SPB; sb += SB) {
            // s1: thread = (sl, a-pair, j): 2 a x 8 k outputs
            {
                int j = tid & 7, ap = (tid >> 3) & 7, sl = tid >> 6;
                const float* ub = usb + (sb + sl) * 512 + j * 8;
                float acc[2][8];
#pragma unroll
                for (int h = 0; h < 2; h++)
#pragma unroll
                    for (int k = 0; k < 8; k++) acc[h][k] = 0.f;
#pragma unroll
                for (int i = 0; i < 8; i++) {
                    float4 u0 = *(const float4*)&ub[i * 64];
                    float4 u1 = *(const float4*)&ub[i * 64 + 4];
                    float fa = fs[(ap * 2) * 8 + i];
                    float fb = fs[(ap * 2 + 1) * 8 + i];
                    acc[0][0] += fa * u0.x; acc[0][1] += fa * u0.y;
                    acc[0][2] += fa * u0.z; acc[0][3] += fa * u0.w;
                    acc[0][4] += fa * u1.x; acc[0][5] += fa * u1.y;
                    acc[0][6] += fa * u1.z; acc[0][7] += fa * u1.w;
                    acc[1][0] += fb * u0.x; acc[1][1] += fb * u0.y;
                    acc[1][2] += fb * u0.z; acc[1][3] += fb * u0.w;
                    acc[1][4] += fb * u1.x; acc[1][5] += fb * u1.y;
                    acc[1][6] += fb * u1.z; acc[1][7] += fb * u1.w;
                }
                float* sp = s1 + sl * 1024 + (ap * 2) * 64 + j * 8;
#pragma unroll
                for (int h = 0; h < 2; h++) {
                    *(float4*)&sp[h * 64]     = make_float4(acc[h][0], acc[h][1], acc[h][2], acc[h][3]);
                    *(float4*)&sp[h * 64 + 4] = make_float4(acc[h][4], acc[h][5], acc[h][6], acc[h][7]);
                }
            }
            __syncthreads();
            // final: r = sl*256 + a*16 + b
#pragma unroll
            for (int it = 0; it < 4; it++) {
                int r = it * THREADS + tid;
                int b = r & 15, a = (r >> 4) & 15, sl = r >> 8;
                const float* sp = s1 + sl * 1024 + a * 64;
                float w[8];
#pragma unroll
                for (int k = 0; k < 8; k++) w[k] = 0.f;
#pragma unroll
                for (int j = 0; j < 8; j++) {
                    float fv = fs[128 + b * 8 + j];
                    float4 sa = *(const float4*)&sp[j * 8];
                    float4 sb2 = *(const float4*)&sp[j * 8 + 4];
                    w[0] += fv * sa.x; w[1] += fv * sa.y;
                    w[2] += fv * sa.z; w[3] += fv * sa.w;
                    w[4] += fv * sb2.x; w[5] += fv * sb2.y;
                    w[6] += fv * sb2.z; w[7] += fv * sb2.w;
                }
                float* yo = y + ((size_t)(s0 + sb + sl) << 12) + a * 256 + b * 16;
                const float4* bp = (const float4*)(bias + a * 256 + b * 16);
#pragma unroll
                for (int c4 = 0; c4 < 4; c4++) {
                    float4 bv = __ldg(bp + c4);
                    float out[4] = {bv.x, bv.y, bv.z, bv.w};
#pragma unroll
                    for (int ci = 0; ci < 4; ci++) {
                        int c = c4 * 4 + ci;
                        float4 fa = *(const float4*)&fs[256 + c * 8];
                        float4 fb = *(const float4*)&fs[256 + c * 8 + 4];
                        out[ci] += fa.x * w[0] + fa.y * w[1] + fa.z * w[2] + fa.w * w[3]
                                 + fb.x * w[4] + fb.y * w[5] + fb.z * w[6] + fb.w * w[7];
                    }
                    *(float4*)(yo + c4 * 4) = make_float4(out[0], out[1], out[2], out[3]);
                }
            }
            __syncthreads();
        }
    }
}

extern "C" void kernel_launch(void* const* d_in, const int* in_sizes, int n_in,
                              void* d_out, int out_size) {
    const float* x    = (const float*)d_in[0];
    const float* core = (const float*)d_in[1];
    const float* f0   = (const float*)d_in[2];
    const float* f1   = (const float*)d_in[3];
    const float* f2   = (const float*)d_in[4];
    const float* f3   = (const float*)d_in[5];
    const float* f4   = (const float*)d_in[6];
    const float* f5   = (const float*)d_in[7];
    const float* bias = (const float*)d_in[8];
    float* y = (float*)d_out;

    cudaFuncSetAttribute(tucker_fused, cudaFuncAttributeMaxDynamicSharedMemorySize, SMEM_BYTES);
    tucker_fused<<<256, THREADS, SMEM_BYTES>>>(x, core, f0, f1, f2, f3, f4, f5, bias, y);
}